// round 8
// baseline (speedup 1.0000x reference)
#include <cuda_runtime.h>
#include <cstdint>

// MultiLevelEmbedding: out[b,t,:] = emb_tables[level_ids[b,t], token_ids[b,t], :]
//                                   + level_embed[level_ids[b,t], :]
// B=64, T=1024, L=4, VOCAB=258, D=512 (float32).
//
// R8: single kernel at the ~24.5 us DRAM-writeback wall, with the
// level_embed add done from REGISTERS: each lane preloads all 16 float4 of
// level_embed it can ever need (4 levels x 4 chunks at its lane offset),
// amortized over ~8 rows via a grid-stride loop. Per row the add is a
// warp-uniform 4-way switch + FADD4 + STG -> no extra L1 wavefronts vs the
// pure gather (which is the established wall). No prologue, no sync.
// Index dtype (int64 vs int32) via per-warp ballot on odd 32-bit words of
// token_ids (values < 258 => odd words all-zero iff int64; P(false) ~ 0).

#define D_VEC     128                 // float4 per row (D=512)
#define VOCAB_SZ  258
#define N_POS     (64 * 1024)         // B*T rows
#define N_PAIRS   (N_POS / 2)         // 32768 row-pairs
#define N_BLOCKS  1024                // x8 warps = 8192 warps, 4 pairs each

#define F4ADD(r, a, b)  do { (r).x=(a).x+(b).x; (r).y=(a).y+(b).y; \
                             (r).z=(a).z+(b).z; (r).w=(a).w+(b).w; } while(0)

// Add the 4 in-flight table chunks to one level's register row, store.
#define ST4(A0,A1,A2,A3, B0,B1,B2,B3, O)              \
    do { float4 _r;                                   \
        F4ADD(_r, A0, B0); __stcs((O),          _r);  \
        F4ADD(_r, A1, B1); __stcs((O) + 32,     _r);  \
        F4ADD(_r, A2, B2); __stcs((O) + 64,     _r);  \
        F4ADD(_r, A3, B3); __stcs((O) + 96,     _r);  \
    } while(0)

// Warp-uniform level switch (l in [0,4)).
#define ADD_STORE(L, A0,A1,A2,A3, O)                               \
    switch ((int)(L)) {                                            \
        case 0:  ST4(A0,A1,A2,A3, b00,b01,b02,b03, O); break;      \
        case 1:  ST4(A0,A1,A2,A3, b10,b11,b12,b13, O); break;      \
        case 2:  ST4(A0,A1,A2,A3, b20,b21,b22,b23, O); break;      \
        default: ST4(A0,A1,A2,A3, b30,b31,b32,b33, O); break;      \
    }

__global__ __launch_bounds__(256, 2)
void mle_kernel(const void* __restrict__ level_ids_raw,
                const void* __restrict__ token_ids_raw,
                const float4* __restrict__ emb_tables,
                const float4* __restrict__ level_embed,
                float4* __restrict__ out) {
    const int lane = threadIdx.x & 31;
    const int warp = (blockIdx.x * 256 + threadIdx.x) >> 5;   // 0..8191

    // ---- dtype detection (1 LDG + ballot, warp-uniform) ----
    const uint32_t* tr = (const uint32_t*)token_ids_raw;
    const unsigned nz  = __ballot_sync(0xffffffffu, tr[2 * lane + 1] != 0u);
    const bool is64    = (nz == 0u);

    // ---- preload all level_embed values this lane can need (16 LDG) ----
    const float4* lb = level_embed + lane;
    const float4 b00 = __ldg(lb +   0), b01 = __ldg(lb +  32),
                 b02 = __ldg(lb +  64), b03 = __ldg(lb +  96);
    const float4 b10 = __ldg(lb + 128), b11 = __ldg(lb + 160),
                 b12 = __ldg(lb + 192), b13 = __ldg(lb + 224);
    const float4 b20 = __ldg(lb + 256), b21 = __ldg(lb + 288),
                 b22 = __ldg(lb + 320), b23 = __ldg(lb + 352);
    const float4 b30 = __ldg(lb + 384), b31 = __ldg(lb + 416),
                 b32 = __ldg(lb + 448), b33 = __ldg(lb + 480);

    // ---- grid-stride over row pairs: 8 independent LDG.128 in flight ----
    for (int p = warp; p < N_PAIRS; p += N_BLOCKS * 8) {
        const int pos0 = p * 2;
        const int pos1 = pos0 + 1;

        long long l0, t0, l1, t1;
        if (is64) {
            l0 = ((const long long*)level_ids_raw)[pos0];
            t0 = ((const long long*)token_ids_raw)[pos0];
            l1 = ((const long long*)level_ids_raw)[pos1];
            t1 = ((const long long*)token_ids_raw)[pos1];
        } else {
            l0 = ((const int*)level_ids_raw)[pos0];
            t0 = ((const int*)token_ids_raw)[pos0];
            l1 = ((const int*)level_ids_raw)[pos1];
            t1 = ((const int*)token_ids_raw)[pos1];
        }

        const float4* __restrict__ r0 =
            emb_tables + (l0 * VOCAB_SZ + t0) * D_VEC + lane;
        const float4* __restrict__ r1 =
            emb_tables + (l1 * VOCAB_SZ + t1) * D_VEC + lane;
        float4* __restrict__ o0 = out + (long long)pos0 * D_VEC + lane;
        float4* __restrict__ o1 = out + (long long)pos1 * D_VEC + lane;

        const float4 a0 = __ldg(r0),      a1 = __ldg(r0 + 32),
                     a2 = __ldg(r0 + 64), a3 = __ldg(r0 + 96);
        const float4 c0 = __ldg(r1),      c1 = __ldg(r1 + 32),
                     c2 = __ldg(r1 + 64), c3 = __ldg(r1 + 96);

        ADD_STORE(l0, a0, a1, a2, a3, o0);
        ADD_STORE(l1, c0, c1, c2, c3, o1);
    }
}

extern "C" void kernel_launch(void* const* d_in, const int* in_sizes, int n_in,
                              void* d_out, int out_size) {
    const void*   level_ids  = d_in[0];
    const void*   token_ids  = d_in[1];
    const float4* emb_tables = (const float4*)d_in[2];
    const float4* level_emb  = (const float4*)d_in[3];
    float4*       out        = (float4*)d_out;

    mle_kernel<<<N_BLOCKS, 256>>>(level_ids, token_ids,
                                  emb_tables, level_emb, out);
}

// round 9
// speedup vs baseline: 1.1372x; 1.1372x over previous
#include <cuda_runtime.h>
#include <cstdint>

// MultiLevelEmbedding: out[b,t,:] = emb_tables[level_ids[b,t], token_ids[b,t], :]
//                                   + level_embed[level_ids[b,t], :]
// B=64, T=1024, L=4, VOCAB=258, D=512 (float32).
//
// R9: gather kernel pinned at the ~24.5 us output-write wall (confirmed by 3
// structurally different kernels in R3/R5/R7); the only recoverable time is
// the exposed fuse-prologue. This round: PDL (as R7) + a faster fuse kernel:
// grid (43,4) x 384, l = blockIdx.y (no div), 2 float4/thread with a shared
// level_embed load (j and j+16512 have equal column mod 128) -> MLP 3,
// 172 blocks instead of 516.
// Index dtype (int64 vs int32) via per-warp ballot on odd 32-bit words of
// token_ids (values < 258 => odd words all-zero iff int64; P(false) ~ 0).

#define D_VEC     128                 // float4 per row (D=512)
#define VOCAB_SZ  258
#define L_LVL     4
#define N_POS     (64 * 1024)         // B*T rows
#define LVL_VEC   (VOCAB_SZ * D_VEC)  // 33024 float4 per level
#define HALF_LVL  (LVL_VEC / 2)       // 16512
#define FUSED_N   (L_LVL * LVL_VEC)   // 132096 float4 = 2.1 MB

__device__ float4 g_fused[FUSED_N];

__global__ __launch_bounds__(384)
void fuse_kernel(const float4* __restrict__ emb_tables,
                 const float4* __restrict__ level_embed) {
    const int l    = blockIdx.y;                       // level, no div
    const int j    = blockIdx.x * 384 + threadIdx.x;   // 0..16511 (43*384)
    const int c    = j & (D_VEC - 1);                  // column (shared: 16512%128==0)
    const int base = l * LVL_VEC;

    // 3 independent loads (MLP 3), one b serves both halves.
    const float4 a0 = __ldg(emb_tables + base + j);
    const float4 a1 = __ldg(emb_tables + base + j + HALF_LVL);
    const float4 b  = __ldg(level_embed + l * D_VEC + c);

    float4 r0, r1;
    r0.x = a0.x + b.x; r0.y = a0.y + b.y; r0.z = a0.z + b.z; r0.w = a0.w + b.w;
    r1.x = a1.x + b.x; r1.y = a1.y + b.y; r1.z = a1.z + b.z; r1.w = a1.w + b.w;
    g_fused[base + j]            = r0;
    g_fused[base + j + HALF_LVL] = r1;
}

__global__ __launch_bounds__(256)
void gather_kernel(const void* __restrict__ level_ids_raw,
                   const void* __restrict__ token_ids_raw,
                   float4* __restrict__ out) {
    const int lane = threadIdx.x & 31;
    const int warp = (blockIdx.x * 256 + threadIdx.x) >> 5;
    const int pos0 = warp * 2;                        // this warp's 2 rows
    const int pos1 = pos0 + 1;

    // ---- pre-sync work: dtype detection (1 LDG + ballot) ----
    const uint32_t* tr = (const uint32_t*)token_ids_raw;
    const unsigned nz  = __ballot_sync(0xffffffffu, tr[2 * lane + 1] != 0u);
    const bool is64    = (nz == 0u);

    // ---- pre-sync work: warp-uniform index loads (broadcast) ----
    long long l0, t0, l1, t1;
    if (is64) {
        l0 = ((const long long*)level_ids_raw)[pos0];
        t0 = ((const long long*)token_ids_raw)[pos0];
        l1 = ((const long long*)level_ids_raw)[pos1];
        t1 = ((const long long*)token_ids_raw)[pos1];
    } else {
        l0 = ((const int*)level_ids_raw)[pos0];
        t0 = ((const int*)token_ids_raw)[pos0];
        l1 = ((const int*)level_ids_raw)[pos1];
        t1 = ((const int*)token_ids_raw)[pos1];
    }

    const float4* __restrict__ r0 = g_fused + (l0 * VOCAB_SZ + t0) * D_VEC;
    const float4* __restrict__ r1 = g_fused + (l1 * VOCAB_SZ + t1) * D_VEC;
    float4* __restrict__ o0 = out + (long long)pos0 * D_VEC;
    float4* __restrict__ o1 = out + (long long)pos1 * D_VEC;

    // ---- wait for fuse_kernel's writes to be visible ----
    cudaGridDependencySynchronize();

    // ---- 8 independent loads first (MLP), then streaming stores ----
    float4 a0 = __ldg(r0 + lane);
    float4 a1 = __ldg(r0 + lane + 32);
    float4 a2 = __ldg(r0 + lane + 64);
    float4 a3 = __ldg(r0 + lane + 96);
    float4 b0 = __ldg(r1 + lane);
    float4 b1 = __ldg(r1 + lane + 32);
    float4 b2 = __ldg(r1 + lane + 64);
    float4 b3 = __ldg(r1 + lane + 96);

    __stcs(o0 + lane,      a0);
    __stcs(o0 + lane + 32, a1);
    __stcs(o0 + lane + 64, a2);
    __stcs(o0 + lane + 96, a3);
    __stcs(o1 + lane,      b0);
    __stcs(o1 + lane + 32, b1);
    __stcs(o1 + lane + 64, b2);
    __stcs(o1 + lane + 96, b3);
}

extern "C" void kernel_launch(void* const* d_in, const int* in_sizes, int n_in,
                              void* d_out, int out_size) {
    const void*   level_ids  = d_in[0];
    const void*   token_ids  = d_in[1];
    const float4* emb_tables = (const float4*)d_in[2];
    const float4* level_emb  = (const float4*)d_in[3];
    float4*       out        = (float4*)d_out;

    // Prologue: build fused table. grid (43,4) x 384 covers 2*43*384*4
    // = 132096 float4 exactly.
    fuse_kernel<<<dim3(43, 4), 384>>>(emb_tables, level_emb);

    // Main gather under programmatic stream serialization: blocks launch
    // while fuse drains, do index work, sync, then stream.
    cudaLaunchConfig_t cfg = {};
    cfg.gridDim  = dim3(N_POS / 16);   // 2 rows/warp, 8 warps/block -> 4096
    cfg.blockDim = dim3(256);
    cfg.dynamicSmemBytes = 0;
    cfg.stream = 0;

    cudaLaunchAttribute attrs[1];
    attrs[0].id = cudaLaunchAttributeProgrammaticStreamSerialization;
    attrs[0].val.programmaticStreamSerializationAllowed = 1;
    cfg.attrs    = attrs;
    cfg.numAttrs = 1;

    cudaLaunchKernelEx(&cfg, gather_kernel,
                       (const void*)level_ids, (const void*)token_ids, out);
}